// round 6
// baseline (speedup 1.0000x reference)
#include <cuda_runtime.h>
#include <cstdint>

// LWTA over groups of 4 consecutive fp32. Pure HBM-streaming kernel.
// R5: 256-bit loads/stores (sm_100+ ld/st.global.v8.f32). Each thread moves
// 64B via 2x LDG.256 + 2x STG.256 — half the L1tex wavefront-queue entries
// and LSU issues per byte vs float4. Exact tiling, no guards.

#define NT 512          // threads per block
#define CPT 2           // 32B chunks per thread (each chunk = 2 LWTA groups)

__device__ __forceinline__ void ldg256(const float* __restrict__ p, float r[8]) {
    asm volatile("ld.global.v8.f32 {%0,%1,%2,%3,%4,%5,%6,%7}, [%8];"
                 : "=f"(r[0]), "=f"(r[1]), "=f"(r[2]), "=f"(r[3]),
                   "=f"(r[4]), "=f"(r[5]), "=f"(r[6]), "=f"(r[7])
                 : "l"(p));
}

__device__ __forceinline__ void stg256(float* __restrict__ p, const float r[8]) {
    asm volatile("st.global.v8.f32 [%0], {%1,%2,%3,%4,%5,%6,%7,%8};"
                 :: "l"(p),
                    "f"(r[0]), "f"(r[1]), "f"(r[2]), "f"(r[3]),
                    "f"(r[4]), "f"(r[5]), "f"(r[6]), "f"(r[7])
                 : "memory");
}

__device__ __forceinline__ void lwta_group4(const float* x, float* r) {
    // argmax with first-max-wins (strict >), matching jnp.argmax
    float m = x[0];
    int w = 0;
    if (x[1] > m) { m = x[1]; w = 1; }
    if (x[2] > m) { m = x[2]; w = 2; }
    if (x[3] > m) { m = x[3]; w = 3; }
    r[0] = (w == 0) ? x[0] : 0.0f;
    r[1] = (w == 1) ? x[1] : 0.0f;
    r[2] = (w == 2) ? x[2] : 0.0f;
    r[3] = (w == 3) ? x[3] : 0.0f;
}

__global__ void __launch_bounds__(NT) lwta_kernel(const float* __restrict__ in,
                                                  float* __restrict__ out) {
    // chunk index (32B granules), coalesced: thread t in sweep k hits
    // chunk base + k*NT + t
    int chunk0 = blockIdx.x * (NT * CPT) + threadIdx.x;

    float v[CPT][8];

    // independent 256-bit loads (MLP = CPT per thread, warp-level beyond that)
#pragma unroll
    for (int k = 0; k < CPT; k++) {
        ldg256(in + (size_t)(chunk0 + k * NT) * 8, v[k]);
    }

    float r[CPT][8];
#pragma unroll
    for (int k = 0; k < CPT; k++) {
        lwta_group4(&v[k][0], &r[k][0]);
        lwta_group4(&v[k][4], &r[k][4]);
    }

#pragma unroll
    for (int k = 0; k < CPT; k++) {
        stg256(out + (size_t)(chunk0 + k * NT) * 8, r[k]);
    }
}

extern "C" void kernel_launch(void* const* d_in, const int* in_sizes, int n_in,
                              void* d_out, int out_size) {
    const float* in = (const float*)d_in[0];
    float* out = (float*)d_out;
    int n_elems = in_sizes[0];                  // 4096*8192 = 33554432
    int n_chunks = n_elems / 8;                 // 4194304 32B chunks

    int chunks_per_block = NT * CPT;            // 1024
    int blocks = n_chunks / chunks_per_block;   // 4096, exact
    lwta_kernel<<<blocks, NT>>>(in, out);
}